// round 14
// baseline (speedup 1.0000x reference)
#include <cuda_runtime.h>
#include <cuda_fp16.h>

// DifferentiableJPEG on GB300:
//   x[32,512,512,3] fp32 -> y[32,512,512,3], Xq[32*3*4096,8,8]
// d_out = [ y | Xq ] fp32.
//
// r13 (smem-staged coalesced x/y I/O, the big win) + r10's Xq staging:
// quantized columns are written to warp-private smem scratch, read back as
// rows, and stored with contiguous STG.128 (24 STG.32 -> 6 STG.128 per
// thread; ~96 -> ~24 L1 wavefronts/warp). All scratch regions warp-private,
// syncwarp-fenced. Y scalar, Cb/Cr packed f32x2.

typedef unsigned long long u64;

static __device__ __forceinline__ u64 pk2(float lo, float hi) {
    u64 r; asm("mov.b64 %0, {%1, %2};" : "=l"(r) : "f"(lo), "f"(hi)); return r;
}
static __device__ __forceinline__ void up2(u64 v, float& lo, float& hi) {
    asm("mov.b64 {%0, %1}, %2;" : "=f"(lo), "=f"(hi) : "l"(v));
}
static __device__ __forceinline__ u64 bc2(float c) {
    u64 r; asm("mov.b64 %0, {%1, %1};" : "=l"(r) : "f"(c)); return r;
}
static __device__ __forceinline__ u64 f2add(u64 a, u64 b) {
    u64 d; asm("add.rn.f32x2 %0, %1, %2;" : "=l"(d) : "l"(a), "l"(b)); return d;
}
static __device__ __forceinline__ u64 f2mul(u64 a, u64 b) {
    u64 d; asm("mul.rn.f32x2 %0, %1, %2;" : "=l"(d) : "l"(a), "l"(b)); return d;
}
static __device__ __forceinline__ u64 f2fma(u64 a, u64 b, u64 c) {
    u64 d; asm("fma.rn.f32x2 %0, %1, %2, %3;" : "=l"(d) : "l"(a), "l"(b), "l"(c)); return d;
}
#define F2SUB(a, b) f2fma((b), N1, (a))

static __device__ __forceinline__ float round_sin5(float u) {
    float r  = u - rintf(u);
    float a  = 6.283185307179586f * r;
    float s1, c1;
    __sincosf(a, &s1, &c1);
    float tc = 2.0f * c1;
    float s2 = tc * s1;
    float s3 = fmaf(tc, s2, -s1);
    float s4 = fmaf(tc, s3, -s2);
    float s5 = fmaf(tc, s4, -s3);
    float S  = 0.3183098861837907f  * s1
             - 0.15915494309189535f * s2
             + 0.10610329539459689f * s3
             - 0.07957747154594767f * s4
             + 0.06366197723675814f * s5;
    return u - S;
}

static __device__ __forceinline__ u64 round_sin5_2(u64 u, u64 N1) {
    float ul, uh; up2(u, ul, uh);
    float rl = ul - rintf(ul), rh = uh - rintf(uh);
    float al = 6.283185307179586f * rl;
    float ah = 6.283185307179586f * rh;
    float sl, cl, sh, ch;
    __sincosf(al, &sl, &cl);
    __sincosf(ah, &sh, &ch);
    u64 s1 = pk2(sl, sh);
    u64 tc = pk2(cl + cl, ch + ch);
    u64 s2 = f2mul(tc, s1);
    u64 s3 = f2fma(tc, s2, f2mul(s1, N1));
    u64 s4 = f2fma(tc, s3, f2mul(s2, N1));
    u64 s5 = f2fma(tc, s4, f2mul(s3, N1));
    u64 S  = f2mul(bc2(0.3183098861837907f), s1);
    S = f2fma(bc2(-0.15915494309189535f), s2, S);
    S = f2fma(bc2(0.10610329539459689f),  s3, S);
    S = f2fma(bc2(-0.07957747154594767f), s4, S);
    S = f2fma(bc2(0.06366197723675814f),  s5, S);
    return f2fma(S, N1, u);
}

static __device__ __forceinline__ void fdct8(const float a[8], float o[8]) {
    float e0 = a[0] + a[7], e1 = a[1] + a[6], e2 = a[2] + a[5], e3 = a[3] + a[4];
    float d0 = a[0] - a[7], d1 = a[1] - a[6], d2 = a[2] - a[5], d3 = a[3] - a[4];
    float g0 = e0 + e3, g1 = e1 + e2, g2 = e0 - e3, g3 = e1 - e2;
    o[0] = 0.3536f * (g0 + g1);
    o[4] = 0.3536f * (g0 - g1);
    o[2] = fmaf( 0.4619f, g2,  0.1913f * g3);
    o[6] = fmaf(-0.4619f, g3,  0.1913f * g2);
    o[1] = fmaf(0.4904f, d0, fmaf( 0.4157f, d1, fmaf( 0.2778f, d2,  0.0975f * d3)));
    o[3] = fmaf(0.4157f, d0, fmaf(-0.0975f, d1, fmaf(-0.4904f, d2, -0.2778f * d3)));
    o[5] = fmaf(0.2778f, d0, fmaf(-0.4904f, d1, fmaf( 0.0975f, d2,  0.4157f * d3)));
    o[7] = fmaf(0.0975f, d0, fmaf(-0.2778f, d1, fmaf( 0.4157f, d2, -0.4904f * d3)));
}

static __device__ __forceinline__ void idct8(const float a[8], float o[8]) {
    float t0 = 0.3536f * (a[0] + a[4]);
    float t1 = 0.3536f * (a[0] - a[4]);
    float u0 = fmaf(0.4619f, a[2],  0.1913f * a[6]);
    float u1 = fmaf(0.1913f, a[2], -0.4619f * a[6]);
    float E0 = t0 + u0, E1 = t1 + u1, E2 = t1 - u1, E3 = t0 - u0;
    float D0 = fmaf(0.4904f, a[1], fmaf( 0.4157f, a[3], fmaf( 0.2778f, a[5],  0.0975f * a[7])));
    float D1 = fmaf(0.4157f, a[1], fmaf(-0.0975f, a[3], fmaf(-0.4904f, a[5], -0.2778f * a[7])));
    float D2 = fmaf(0.2778f, a[1], fmaf(-0.4904f, a[3], fmaf( 0.0975f, a[5],  0.4157f * a[7])));
    float D3 = fmaf(0.0975f, a[1], fmaf(-0.2778f, a[3], fmaf( 0.4157f, a[5], -0.4904f * a[7])));
    o[0] = E0 + D0;  o[7] = E0 - D0;
    o[1] = E1 + D1;  o[6] = E1 - D1;
    o[2] = E2 + D2;  o[5] = E2 - D2;
    o[3] = E3 + D3;  o[4] = E3 - D3;
}

static __device__ __forceinline__ void fdct8_2(const u64 a[8], u64 o[8], u64 N1) {
    u64 e0 = f2add(a[0], a[7]), e1 = f2add(a[1], a[6]);
    u64 e2 = f2add(a[2], a[5]), e3 = f2add(a[3], a[4]);
    u64 d0 = F2SUB(a[0], a[7]), d1 = F2SUB(a[1], a[6]);
    u64 d2 = F2SUB(a[2], a[5]), d3 = F2SUB(a[3], a[4]);
    u64 g0 = f2add(e0, e3), g1 = f2add(e1, e2);
    u64 g2 = F2SUB(e0, e3), g3 = F2SUB(e1, e2);
    o[0] = f2mul(bc2(0.3536f), f2add(g0, g1));
    o[4] = f2mul(bc2(0.3536f), F2SUB(g0, g1));
    o[2] = f2fma(bc2( 0.4619f), g2, f2mul(bc2(0.1913f), g3));
    o[6] = f2fma(bc2(-0.4619f), g3, f2mul(bc2(0.1913f), g2));
    o[1] = f2fma(bc2(0.4904f), d0, f2fma(bc2( 0.4157f), d1, f2fma(bc2( 0.2778f), d2, f2mul(bc2( 0.0975f), d3))));
    o[3] = f2fma(bc2(0.4157f), d0, f2fma(bc2(-0.0975f), d1, f2fma(bc2(-0.4904f), d2, f2mul(bc2(-0.2778f), d3))));
    o[5] = f2fma(bc2(0.2778f), d0, f2fma(bc2(-0.4904f), d1, f2fma(bc2( 0.0975f), d2, f2mul(bc2( 0.4157f), d3))));
    o[7] = f2fma(bc2(0.0975f), d0, f2fma(bc2(-0.2778f), d1, f2fma(bc2( 0.4157f), d2, f2mul(bc2(-0.4904f), d3))));
}

static __device__ __forceinline__ void idct8_2(const u64 a[8], u64 o[8], u64 N1) {
    u64 t0 = f2mul(bc2(0.3536f), f2add(a[0], a[4]));
    u64 t1 = f2mul(bc2(0.3536f), F2SUB(a[0], a[4]));
    u64 u0 = f2fma(bc2(0.4619f), a[2], f2mul(bc2( 0.1913f), a[6]));
    u64 u1 = f2fma(bc2(0.1913f), a[2], f2mul(bc2(-0.4619f), a[6]));
    u64 E0 = f2add(t0, u0), E1 = f2add(t1, u1);
    u64 E2 = F2SUB(t1, u1), E3 = F2SUB(t0, u0);
    u64 D0 = f2fma(bc2(0.4904f), a[1], f2fma(bc2( 0.4157f), a[3], f2fma(bc2( 0.2778f), a[5], f2mul(bc2( 0.0975f), a[7]))));
    u64 D1 = f2fma(bc2(0.4157f), a[1], f2fma(bc2(-0.0975f), a[3], f2fma(bc2(-0.4904f), a[5], f2mul(bc2(-0.2778f), a[7]))));
    u64 D2 = f2fma(bc2(0.2778f), a[1], f2fma(bc2(-0.4904f), a[3], f2fma(bc2( 0.0975f), a[5], f2mul(bc2( 0.4157f), a[7]))));
    u64 D3 = f2fma(bc2(0.0975f), a[1], f2fma(bc2(-0.2778f), a[3], f2fma(bc2( 0.4157f), a[5], f2mul(bc2(-0.4904f), a[7]))));
    o[0] = f2add(E0, D0);  o[7] = F2SUB(E0, D0);
    o[1] = f2add(E1, D1);  o[6] = F2SUB(E1, D1);
    o[2] = f2add(E2, D2);  o[5] = F2SUB(E2, D2);
    o[3] = f2add(E3, D3);  o[4] = F2SUB(E3, D3);
}

// staging: 8 image rows, 772-float stride (3088B) -> conflict-free per-
// thread row reads. Data = 768 floats/row.
#define SROW 772
// per-warp private scratch: 704 floats (2816B, 0 mod 128).
#define WSCR 704
#define TROW 12
#define TTILE 104
#define UROW 10
#define UTILE 88

__global__ __launch_bounds__(256, 4)
void jpeg_kernel(const float* __restrict__ x,
                 const float* __restrict__ q_luma,
                 const float* __restrict__ q_chroma,
                 float* __restrict__ y_out,
                 float* __restrict__ xq_out)
{
    __shared__ __align__(16) float stage[8 * SROW];   // 24.1 KB, multi-purpose

    const u64 N1 = bc2(-1.0f);

    const int tid = threadIdx.x;
    const int t  = tid >> 3;            // tile within CTA (0..31)
    const int r  = tid & 7;             // row within tile
    const int tg = blockIdx.x * 32 + t;
    const int tgb = blockIdx.x * 32;
    const int b   = tgb >> 12;
    const int bh  = (tgb & 4095) >> 6;
    const int bw0 = tgb & 63;

    // per-warp private scratch views
    float* sw = stage + (tid >> 5) * WSCR;
    float* sf = sw + (t & 3) * TTILE;
    u64*   su = (u64*)sw + (t & 3) * UTILE;

    // ---- 1. cooperative coalesced load: x region -> stage ----
    const float* xbase = x + ((size_t)(b * 512 + bh * 8) * 512 + bw0 * 8) * 3;
#pragma unroll
    for (int i = 0; i < 6; i++) {
        int idx4 = tid + i * 256;
        int row  = idx4 / 192;
        int c4   = idx4 - row * 192;
        float4 v = *(const float4*)(xbase + row * 1536 + c4 * 4);
        *(float4*)(stage + row * SROW + c4 * 4) = v;
    }
    __syncthreads();

    // Q columns (column r), packed half2 (exact: integers <= 255)
    __half2 qh[2][4];
#pragma unroll
    for (int j = 0; j < 4; j++) {
        qh[0][j] = __floats2half2_rn(q_luma  [(2*j  ) * 8 + r], q_luma  [(2*j+1) * 8 + r]);
        qh[1][j] = __floats2half2_rn(q_chroma[(2*j  ) * 8 + r], q_chroma[(2*j+1) * 8 + r]);
    }

    // ---- 2. per-thread: read my 24 floats from stage ----
    float px[24];
    {
        const float4* sp = (const float4*)(stage + r * SROW + t * 24);
#pragma unroll
        for (int v = 0; v < 6; v++) {
            float4 q4 = sp[v];
            px[v*4+0] = q4.x; px[v*4+1] = q4.y; px[v*4+2] = q4.z; px[v*4+3] = q4.w;
        }
    }
    __syncthreads();   // inputs consumed before scratch overlays write

    // RGB -> YCbCr - 127; Y scalar, Cb/Cr packed
    float yy[8];
    u64 P[8];
#pragma unroll
    for (int p = 0; p < 8; p++) {
        float R = 255.0f * px[3*p+0];
        float G = 255.0f * px[3*p+1];
        float Bv= 255.0f * px[3*p+2];
        yy[p] = fmaf(0.299f, R, fmaf(0.587f, G, 0.114f * Bv)) - 127.0f;
        float cb = fmaf(-0.168736f, R, fmaf(-0.331264f, G,  0.5f      * Bv)) + 1.0f;
        float cr = fmaf(0.5f,       R, fmaf(-0.418688f, G, -0.081312f * Bv)) + 1.0f;
        P[p] = pk2(cb, cr);
    }

    const size_t blk64 = ((size_t)(b * 3 * 4096 + (tg & 4095))) << 6;

    // ======== Y channel (scalar), warp-local scratch ========
    {
        float a[8], o[8];
#pragma unroll
        for (int j = 0; j < 8; j++) a[j] = yy[j];
        fdct8(a, o);

        {   // transpose 1
            float4* sp = (float4*)(sf + r * TROW);
            sp[0] = make_float4(o[0], o[1], o[2], o[3]);
            sp[1] = make_float4(o[4], o[5], o[6], o[7]);
        }
        __syncwarp();
#pragma unroll
        for (int j = 0; j < 8; j++) a[j] = sf[j * TROW + r];
        __syncwarp();

        fdct8(a, o);

        // quantize + soft round (column-held)
#pragma unroll
        for (int j = 0; j < 8; j++) {
            __half2 h2 = qh[0][j >> 1];
            float qf = (j & 1) ? __high2float(h2) : __low2float(h2);
            float u  = __fdividef(o[j], qf);
            a[j] = round_sin5(u) * qf;
        }

        // stage Xq: columns -> sf, read row r, contiguous STG.128
#pragma unroll
        for (int j = 0; j < 8; j++) sf[j * TROW + r] = a[j];
        __syncwarp();
        {
            float4 w0 = *(const float4*)(sf + r * TROW);
            float4 w1 = *(const float4*)(sf + r * TROW + 4);
            float4* xp = (float4*)(xq_out + blk64 + r * 8);
            xp[0] = w0;
            xp[1] = w1;
        }

        idct8(a, o);       // S3 from register-held columns
        __syncwarp();      // staging reads done before transpose-2 writes
        {   // transpose 2
            float4* sp = (float4*)(sf + r * TROW);
            sp[0] = make_float4(o[0], o[1], o[2], o[3]);
            sp[1] = make_float4(o[4], o[5], o[6], o[7]);
        }
        __syncwarp();
#pragma unroll
        for (int j = 0; j < 8; j++) a[j] = sf[j * TROW + r];
        __syncwarp();      // done with float view before u64 view overwrites

        idct8(a, yy);      // yy now holds ib_Y row r
    }

    // ======== Cb/Cr pair (packed f32x2), warp-local scratch ========
    u64 A[8], O[8];
#pragma unroll
    for (int j = 0; j < 8; j++) A[j] = P[j];
    fdct8_2(A, O, N1);

    {   // transpose 1: vectorized row store (4x STS.128)
        ulonglong2* sp = (ulonglong2*)(su + r * UROW);
        sp[0] = make_ulonglong2(O[0], O[1]);
        sp[1] = make_ulonglong2(O[2], O[3]);
        sp[2] = make_ulonglong2(O[4], O[5]);
        sp[3] = make_ulonglong2(O[6], O[7]);
    }
    __syncwarp();
#pragma unroll
    for (int j = 0; j < 8; j++) A[j] = su[j * UROW + r];
    __syncwarp();

    fdct8_2(A, O, N1);

#pragma unroll
    for (int j = 0; j < 8; j++) {
        __half2 h2 = qh[1][j >> 1];
        float qf = (j & 1) ? __high2float(h2) : __low2float(h2);
        float rq = __fdividef(1.0f, qf);
        u64 u = f2mul(O[j], bc2(rq));
        A[j] = f2mul(round_sin5_2(u, N1), bc2(qf));
    }

    // stage chroma Xq: columns -> su, read row r, deinterleave, STG.128
#pragma unroll
    for (int j = 0; j < 8; j++) su[j * UROW + r] = A[j];
    __syncwarp();
    {
        const ulonglong2* sp = (const ulonglong2*)(su + r * UROW);
        ulonglong2 p0 = sp[0], p1 = sp[1], p2 = sp[2], p3 = sp[3];
        float cb0, cr0, cb1, cr1, cb2, cr2, cb3, cr3;
        float cb4, cr4, cb5, cr5, cb6, cr6, cb7, cr7;
        up2(p0.x, cb0, cr0); up2(p0.y, cb1, cr1);
        up2(p1.x, cb2, cr2); up2(p1.y, cb3, cr3);
        up2(p2.x, cb4, cr4); up2(p2.y, cb5, cr5);
        up2(p3.x, cb6, cr6); up2(p3.y, cb7, cr7);
        float4* x1 = (float4*)(xq_out + blk64 + (size_t)(4096 * 64)     + r * 8);
        float4* x2 = (float4*)(xq_out + blk64 + (size_t)(2 * 4096 * 64) + r * 8);
        x1[0] = make_float4(cb0, cb1, cb2, cb3);
        x1[1] = make_float4(cb4, cb5, cb6, cb7);
        x2[0] = make_float4(cr0, cr1, cr2, cr3);
        x2[1] = make_float4(cr4, cr5, cr6, cr7);
    }

    idct8_2(A, O, N1);     // S3 from register-held columns
    __syncwarp();          // staging reads done before transpose-2 writes
    {   // transpose 2
        ulonglong2* sp = (ulonglong2*)(su + r * UROW);
        sp[0] = make_ulonglong2(O[0], O[1]);
        sp[1] = make_ulonglong2(O[2], O[3]);
        sp[2] = make_ulonglong2(O[4], O[5]);
        sp[3] = make_ulonglong2(O[6], O[7]);
    }
    __syncwarp();
#pragma unroll
    for (int j = 0; j < 8; j++) A[j] = su[j * UROW + r];

    idct8_2(A, O, N1);     // O[p] = packed (ib_Cb, ib_Cr) for pixel p

    // YCbCr -> RGB, /255, clip
#pragma unroll
    for (int p = 0; p < 8; p++) {
        float cbv, crv; up2(O[p], cbv, crv);
        float Y  = yy[p] + 127.0f;
        float Cb = cbv  + 127.0f;
        float Cr = crv  + 127.0f;
        float R = fmaf(1.402f,  Cr, Y) + (-1.402f  * 128.0f);
        float G = fmaf(-0.344136f, Cb, fmaf(-0.714136f, Cr, Y)) + (1.058272f * 128.0f);
        float Bv= fmaf(1.772f,  Cb, Y) + (-1.772f  * 128.0f);
        px[3*p+0] = fminf(fmaxf(R  * (1.0f/255.0f), 0.0f), 1.0f);
        px[3*p+1] = fminf(fmaxf(G  * (1.0f/255.0f), 0.0f), 1.0f);
        px[3*p+2] = fminf(fmaxf(Bv * (1.0f/255.0f), 0.0f), 1.0f);
    }

    // ---- 3. stage y rows back ----
    __syncthreads();
    {
        float4* sp = (float4*)(stage + r * SROW + t * 24);
#pragma unroll
        for (int v = 0; v < 6; v++) {
            float4 q4;
            q4.x = px[v*4+0]; q4.y = px[v*4+1]; q4.z = px[v*4+2]; q4.w = px[v*4+3];
            sp[v] = q4;
        }
    }
    __syncthreads();

    // ---- 4. cooperative coalesced store: stage -> y_out ----
    float* ybase = y_out + ((size_t)(b * 512 + bh * 8) * 512 + bw0 * 8) * 3;
#pragma unroll
    for (int i = 0; i < 6; i++) {
        int idx4 = tid + i * 256;
        int row  = idx4 / 192;
        int c4   = idx4 - row * 192;
        float4 v = *(const float4*)(stage + row * SROW + c4 * 4);
        *(float4*)(ybase + row * 1536 + c4 * 4) = v;
    }
}

extern "C" void kernel_launch(void* const* d_in, const int* in_sizes, int n_in,
                              void* d_out, int out_size)
{
    const float* x  = (const float*)d_in[0];
    const float* ql = (const float*)d_in[1];
    const float* qc = (const float*)d_in[2];

    float* y  = (float*)d_out;
    float* xq = (float*)d_out + (size_t)32 * 512 * 512 * 3;

    jpeg_kernel<<<4096, 256>>>(x, ql, qc, y, xq);
}

// round 15
// speedup vs baseline: 1.0987x; 1.0987x over previous
#include <cuda_runtime.h>
#include <cuda_fp16.h>

// DifferentiableJPEG on GB300:
//   x[32,512,512,3] fp32 -> y[32,512,512,3], Xq[32*3*4096,8,8]
// d_out = [ y | Xq ] fp32.
//
// r13 base (smem-staged coalesced x/y I/O; scattered Xq stores are at the
// cache-line minimum) + INTERLEAVED Y / CbCr pipelines: the two independent
// chains run stage-by-stage together, doubling ILP and sharing transpose
// sync windows (8 -> 5 syncwarps). Per-warp scratch: disjoint Y-float and
// CbCr-u64 regions, union-allocated with the I/O stage buffer.

typedef unsigned long long u64;

static __device__ __forceinline__ u64 pk2(float lo, float hi) {
    u64 r; asm("mov.b64 %0, {%1, %2};" : "=l"(r) : "f"(lo), "f"(hi)); return r;
}
static __device__ __forceinline__ void up2(u64 v, float& lo, float& hi) {
    asm("mov.b64 {%0, %1}, %2;" : "=f"(lo), "=f"(hi) : "l"(v));
}
static __device__ __forceinline__ u64 bc2(float c) {
    u64 r; asm("mov.b64 %0, {%1, %1};" : "=l"(r) : "f"(c)); return r;
}
static __device__ __forceinline__ u64 f2add(u64 a, u64 b) {
    u64 d; asm("add.rn.f32x2 %0, %1, %2;" : "=l"(d) : "l"(a), "l"(b)); return d;
}
static __device__ __forceinline__ u64 f2mul(u64 a, u64 b) {
    u64 d; asm("mul.rn.f32x2 %0, %1, %2;" : "=l"(d) : "l"(a), "l"(b)); return d;
}
static __device__ __forceinline__ u64 f2fma(u64 a, u64 b, u64 c) {
    u64 d; asm("fma.rn.f32x2 %0, %1, %2, %3;" : "=l"(d) : "l"(a), "l"(b), "l"(c)); return d;
}
#define F2SUB(a, b) f2fma((b), N1, (a))

static __device__ __forceinline__ float round_sin5(float u) {
    float r  = u - rintf(u);
    float a  = 6.283185307179586f * r;
    float s1, c1;
    __sincosf(a, &s1, &c1);
    float tc = 2.0f * c1;
    float s2 = tc * s1;
    float s3 = fmaf(tc, s2, -s1);
    float s4 = fmaf(tc, s3, -s2);
    float s5 = fmaf(tc, s4, -s3);
    float S  = 0.3183098861837907f  * s1
             - 0.15915494309189535f * s2
             + 0.10610329539459689f * s3
             - 0.07957747154594767f * s4
             + 0.06366197723675814f * s5;
    return u - S;
}

static __device__ __forceinline__ u64 round_sin5_2(u64 u, u64 N1) {
    float ul, uh; up2(u, ul, uh);
    float rl = ul - rintf(ul), rh = uh - rintf(uh);
    float al = 6.283185307179586f * rl;
    float ah = 6.283185307179586f * rh;
    float sl, cl, sh, ch;
    __sincosf(al, &sl, &cl);
    __sincosf(ah, &sh, &ch);
    u64 s1 = pk2(sl, sh);
    u64 tc = pk2(cl + cl, ch + ch);
    u64 s2 = f2mul(tc, s1);
    u64 s3 = f2fma(tc, s2, f2mul(s1, N1));
    u64 s4 = f2fma(tc, s3, f2mul(s2, N1));
    u64 s5 = f2fma(tc, s4, f2mul(s3, N1));
    u64 S  = f2mul(bc2(0.3183098861837907f), s1);
    S = f2fma(bc2(-0.15915494309189535f), s2, S);
    S = f2fma(bc2(0.10610329539459689f),  s3, S);
    S = f2fma(bc2(-0.07957747154594767f), s4, S);
    S = f2fma(bc2(0.06366197723675814f),  s5, S);
    return f2fma(S, N1, u);
}

static __device__ __forceinline__ void fdct8(const float a[8], float o[8]) {
    float e0 = a[0] + a[7], e1 = a[1] + a[6], e2 = a[2] + a[5], e3 = a[3] + a[4];
    float d0 = a[0] - a[7], d1 = a[1] - a[6], d2 = a[2] - a[5], d3 = a[3] - a[4];
    float g0 = e0 + e3, g1 = e1 + e2, g2 = e0 - e3, g3 = e1 - e2;
    o[0] = 0.3536f * (g0 + g1);
    o[4] = 0.3536f * (g0 - g1);
    o[2] = fmaf( 0.4619f, g2,  0.1913f * g3);
    o[6] = fmaf(-0.4619f, g3,  0.1913f * g2);
    o[1] = fmaf(0.4904f, d0, fmaf( 0.4157f, d1, fmaf( 0.2778f, d2,  0.0975f * d3)));
    o[3] = fmaf(0.4157f, d0, fmaf(-0.0975f, d1, fmaf(-0.4904f, d2, -0.2778f * d3)));
    o[5] = fmaf(0.2778f, d0, fmaf(-0.4904f, d1, fmaf( 0.0975f, d2,  0.4157f * d3)));
    o[7] = fmaf(0.0975f, d0, fmaf(-0.2778f, d1, fmaf( 0.4157f, d2, -0.4904f * d3)));
}

static __device__ __forceinline__ void idct8(const float a[8], float o[8]) {
    float t0 = 0.3536f * (a[0] + a[4]);
    float t1 = 0.3536f * (a[0] - a[4]);
    float u0 = fmaf(0.4619f, a[2],  0.1913f * a[6]);
    float u1 = fmaf(0.1913f, a[2], -0.4619f * a[6]);
    float E0 = t0 + u0, E1 = t1 + u1, E2 = t1 - u1, E3 = t0 - u0;
    float D0 = fmaf(0.4904f, a[1], fmaf( 0.4157f, a[3], fmaf( 0.2778f, a[5],  0.0975f * a[7])));
    float D1 = fmaf(0.4157f, a[1], fmaf(-0.0975f, a[3], fmaf(-0.4904f, a[5], -0.2778f * a[7])));
    float D2 = fmaf(0.2778f, a[1], fmaf(-0.4904f, a[3], fmaf( 0.0975f, a[5],  0.4157f * a[7])));
    float D3 = fmaf(0.0975f, a[1], fmaf(-0.2778f, a[3], fmaf( 0.4157f, a[5], -0.4904f * a[7])));
    o[0] = E0 + D0;  o[7] = E0 - D0;
    o[1] = E1 + D1;  o[6] = E1 - D1;
    o[2] = E2 + D2;  o[5] = E2 - D2;
    o[3] = E3 + D3;  o[4] = E3 - D3;
}

static __device__ __forceinline__ void fdct8_2(const u64 a[8], u64 o[8], u64 N1) {
    u64 e0 = f2add(a[0], a[7]), e1 = f2add(a[1], a[6]);
    u64 e2 = f2add(a[2], a[5]), e3 = f2add(a[3], a[4]);
    u64 d0 = F2SUB(a[0], a[7]), d1 = F2SUB(a[1], a[6]);
    u64 d2 = F2SUB(a[2], a[5]), d3 = F2SUB(a[3], a[4]);
    u64 g0 = f2add(e0, e3), g1 = f2add(e1, e2);
    u64 g2 = F2SUB(e0, e3), g3 = F2SUB(e1, e2);
    o[0] = f2mul(bc2(0.3536f), f2add(g0, g1));
    o[4] = f2mul(bc2(0.3536f), F2SUB(g0, g1));
    o[2] = f2fma(bc2( 0.4619f), g2, f2mul(bc2(0.1913f), g3));
    o[6] = f2fma(bc2(-0.4619f), g3, f2mul(bc2(0.1913f), g2));
    o[1] = f2fma(bc2(0.4904f), d0, f2fma(bc2( 0.4157f), d1, f2fma(bc2( 0.2778f), d2, f2mul(bc2( 0.0975f), d3))));
    o[3] = f2fma(bc2(0.4157f), d0, f2fma(bc2(-0.0975f), d1, f2fma(bc2(-0.4904f), d2, f2mul(bc2(-0.2778f), d3))));
    o[5] = f2fma(bc2(0.2778f), d0, f2fma(bc2(-0.4904f), d1, f2fma(bc2( 0.0975f), d2, f2mul(bc2( 0.4157f), d3))));
    o[7] = f2fma(bc2(0.0975f), d0, f2fma(bc2(-0.2778f), d1, f2fma(bc2( 0.4157f), d2, f2mul(bc2(-0.4904f), d3))));
}

static __device__ __forceinline__ void idct8_2(const u64 a[8], u64 o[8], u64 N1) {
    u64 t0 = f2mul(bc2(0.3536f), f2add(a[0], a[4]));
    u64 t1 = f2mul(bc2(0.3536f), F2SUB(a[0], a[4]));
    u64 u0 = f2fma(bc2(0.4619f), a[2], f2mul(bc2( 0.1913f), a[6]));
    u64 u1 = f2fma(bc2(0.1913f), a[2], f2mul(bc2(-0.4619f), a[6]));
    u64 E0 = f2add(t0, u0), E1 = f2add(t1, u1);
    u64 E2 = F2SUB(t1, u1), E3 = F2SUB(t0, u0);
    u64 D0 = f2fma(bc2(0.4904f), a[1], f2fma(bc2( 0.4157f), a[3], f2fma(bc2( 0.2778f), a[5], f2mul(bc2( 0.0975f), a[7]))));
    u64 D1 = f2fma(bc2(0.4157f), a[1], f2fma(bc2(-0.0975f), a[3], f2fma(bc2(-0.4904f), a[5], f2mul(bc2(-0.2778f), a[7]))));
    u64 D2 = f2fma(bc2(0.2778f), a[1], f2fma(bc2(-0.4904f), a[3], f2fma(bc2( 0.0975f), a[5], f2mul(bc2( 0.4157f), a[7]))));
    u64 D3 = f2fma(bc2(0.0975f), a[1], f2fma(bc2(-0.2778f), a[3], f2fma(bc2( 0.4157f), a[5], f2mul(bc2(-0.4904f), a[7]))));
    o[0] = f2add(E0, D0);  o[7] = F2SUB(E0, D0);
    o[1] = f2add(E1, D1);  o[6] = F2SUB(E1, D1);
    o[2] = f2add(E2, D2);  o[5] = F2SUB(E2, D2);
    o[3] = f2add(E3, D3);  o[4] = F2SUB(E3, D3);
}

// I/O staging: 8 image rows, 772-float stride (3088B), data 768/row.
#define SROW 772
// per-warp compute scratch: 1120 floats (4480B = 35*128 -> bank-aligned).
//   [0, 416)    float view: Y transposes, 4 tiles x TTILE
//   [416, 1120) u64 view:   CbCr transposes, 4 tiles x UTILE u64
#define WSCR 1120
#define TROW 12
#define TTILE 104
#define UROW 10
#define UTILE 88
// union buffer: max(8*SROW, 8*WSCR) = 8960 floats = 35840B
#define SMTOT 8960

__global__ __launch_bounds__(256, 4)
void jpeg_kernel(const float* __restrict__ x,
                 const float* __restrict__ q_luma,
                 const float* __restrict__ q_chroma,
                 float* __restrict__ y_out,
                 float* __restrict__ xq_out)
{
    __shared__ __align__(16) float smbuf[SMTOT];
    float* stage = smbuf;                        // I/O phases only

    const u64 N1 = bc2(-1.0f);

    const int tid = threadIdx.x;
    const int t  = tid >> 3;            // tile within CTA (0..31)
    const int r  = tid & 7;             // row within tile
    const int tg = blockIdx.x * 32 + t;
    const int tgb = blockIdx.x * 32;
    const int b   = tgb >> 12;
    const int bh  = (tgb & 4095) >> 6;
    const int bw0 = tgb & 63;

    // per-warp compute scratch views (disjoint Y / CbCr regions)
    float* sw = smbuf + (tid >> 5) * WSCR;
    float* sf = sw + (t & 3) * TTILE;
    u64*   su = (u64*)(sw + 416) + (t & 3) * UTILE;

    // ---- 1. cooperative coalesced load: x region -> stage ----
    const float* xbase = x + ((size_t)(b * 512 + bh * 8) * 512 + bw0 * 8) * 3;
#pragma unroll
    for (int i = 0; i < 6; i++) {
        int idx4 = tid + i * 256;
        int row  = idx4 / 192;
        int c4   = idx4 - row * 192;
        float4 v = *(const float4*)(xbase + row * 1536 + c4 * 4);
        *(float4*)(stage + row * SROW + c4 * 4) = v;
    }
    __syncthreads();

    // Q columns (column r), packed half2 (exact: integers <= 255)
    __half2 qh[2][4];
#pragma unroll
    for (int j = 0; j < 4; j++) {
        qh[0][j] = __floats2half2_rn(q_luma  [(2*j  ) * 8 + r], q_luma  [(2*j+1) * 8 + r]);
        qh[1][j] = __floats2half2_rn(q_chroma[(2*j  ) * 8 + r], q_chroma[(2*j+1) * 8 + r]);
    }

    // ---- 2. per-thread: read my 24 floats from stage ----
    float px[24];
    {
        const float4* sp = (const float4*)(stage + r * SROW + t * 24);
#pragma unroll
        for (int v = 0; v < 6; v++) {
            float4 q4 = sp[v];
            px[v*4+0] = q4.x; px[v*4+1] = q4.y; px[v*4+2] = q4.z; px[v*4+3] = q4.w;
        }
    }
    __syncthreads();   // inputs consumed before compute scratch writes

    // RGB -> YCbCr - 127; Y scalar, Cb/Cr packed
    float aY[8];
    u64 AC[8];
#pragma unroll
    for (int p = 0; p < 8; p++) {
        float R = 255.0f * px[3*p+0];
        float G = 255.0f * px[3*p+1];
        float Bv= 255.0f * px[3*p+2];
        aY[p] = fmaf(0.299f, R, fmaf(0.587f, G, 0.114f * Bv)) - 127.0f;
        float cb = fmaf(-0.168736f, R, fmaf(-0.331264f, G,  0.5f      * Bv)) + 1.0f;
        float cr = fmaf(0.5f,       R, fmaf(-0.418688f, G, -0.081312f * Bv)) + 1.0f;
        AC[p] = pk2(cb, cr);
    }

    const size_t blk64 = ((size_t)(b * 3 * 4096 + (tg & 4095))) << 6;

    float oY[8];
    u64 OC[8];

    // ======== interleaved pipelines: S1 ========
    fdct8(aY, oY);
    fdct8_2(AC, OC, N1);

    // ---- merged transpose 1 ----
    {
        float4* sp = (float4*)(sf + r * TROW);
        sp[0] = make_float4(oY[0], oY[1], oY[2], oY[3]);
        sp[1] = make_float4(oY[4], oY[5], oY[6], oY[7]);
        ulonglong2* up = (ulonglong2*)(su + r * UROW);
        up[0] = make_ulonglong2(OC[0], OC[1]);
        up[1] = make_ulonglong2(OC[2], OC[3]);
        up[2] = make_ulonglong2(OC[4], OC[5]);
        up[3] = make_ulonglong2(OC[6], OC[7]);
    }
    __syncwarp();
#pragma unroll
    for (int j = 0; j < 8; j++) {
        aY[j] = sf[j * TROW + r];
        AC[j] = su[j * UROW + r];
    }
    __syncwarp();

    // ======== S2 ========
    fdct8(aY, oY);
    fdct8_2(AC, OC, N1);

    // ======== quantize + soft round (both channels: big ILP pool) ========
#pragma unroll
    for (int j = 0; j < 8; j++) {
        __half2 h2 = qh[0][j >> 1];
        float qf = (j & 1) ? __high2float(h2) : __low2float(h2);
        float u  = __fdividef(oY[j], qf);
        aY[j] = round_sin5(u) * qf;
    }
#pragma unroll
    for (int j = 0; j < 8; j++) {
        __half2 h2 = qh[1][j >> 1];
        float qf = (j & 1) ? __high2float(h2) : __low2float(h2);
        float rq = __fdividef(1.0f, qf);
        u64 u = f2mul(OC[j], bc2(rq));
        AC[j] = f2mul(round_sin5_2(u, N1), bc2(qf));
    }

    // ======== Xq stores (scattered STG.32 = line-minimal) ========
    {
        float* xqp = xq_out + blk64 + r;
#pragma unroll
        for (int j = 0; j < 8; j++) xqp[j * 8] = aY[j];
        float* xq1 = xq_out + blk64 + (size_t)(4096 * 64)     + r;
        float* xq2 = xq_out + blk64 + (size_t)(2 * 4096 * 64) + r;
#pragma unroll
        for (int j = 0; j < 8; j++) {
            float cb, cr; up2(AC[j], cb, cr);
            xq1[j * 8] = cb;
            xq2[j * 8] = cr;
        }
    }

    // ======== S3 ========
    idct8(aY, oY);
    idct8_2(AC, OC, N1);

    // ---- merged transpose 2 ----
    {
        float4* sp = (float4*)(sf + r * TROW);
        sp[0] = make_float4(oY[0], oY[1], oY[2], oY[3]);
        sp[1] = make_float4(oY[4], oY[5], oY[6], oY[7]);
        ulonglong2* up = (ulonglong2*)(su + r * UROW);
        up[0] = make_ulonglong2(OC[0], OC[1]);
        up[1] = make_ulonglong2(OC[2], OC[3]);
        up[2] = make_ulonglong2(OC[4], OC[5]);
        up[3] = make_ulonglong2(OC[6], OC[7]);
    }
    __syncwarp();
#pragma unroll
    for (int j = 0; j < 8; j++) {
        aY[j] = sf[j * TROW + r];
        AC[j] = su[j * UROW + r];
    }

    // ======== S4 ========
    idct8(aY, oY);          // oY = ib_Y row r
    idct8_2(AC, OC, N1);    // OC[p] = packed (ib_Cb, ib_Cr)

    // YCbCr -> RGB, /255, clip
#pragma unroll
    for (int p = 0; p < 8; p++) {
        float cbv, crv; up2(OC[p], cbv, crv);
        float Y  = oY[p] + 127.0f;
        float Cb = cbv  + 127.0f;
        float Cr = crv  + 127.0f;
        float R = fmaf(1.402f,  Cr, Y) + (-1.402f  * 128.0f);
        float G = fmaf(-0.344136f, Cb, fmaf(-0.714136f, Cr, Y)) + (1.058272f * 128.0f);
        float Bv= fmaf(1.772f,  Cb, Y) + (-1.772f  * 128.0f);
        px[3*p+0] = fminf(fmaxf(R  * (1.0f/255.0f), 0.0f), 1.0f);
        px[3*p+1] = fminf(fmaxf(G  * (1.0f/255.0f), 0.0f), 1.0f);
        px[3*p+2] = fminf(fmaxf(Bv * (1.0f/255.0f), 0.0f), 1.0f);
    }

    // ---- 3. stage y rows back (compute scratch use finished CTA-wide) ----
    __syncthreads();
    {
        float4* sp = (float4*)(stage + r * SROW + t * 24);
#pragma unroll
        for (int v = 0; v < 6; v++) {
            float4 q4;
            q4.x = px[v*4+0]; q4.y = px[v*4+1]; q4.z = px[v*4+2]; q4.w = px[v*4+3];
            sp[v] = q4;
        }
    }
    __syncthreads();

    // ---- 4. cooperative coalesced store: stage -> y_out ----
    float* ybase = y_out + ((size_t)(b * 512 + bh * 8) * 512 + bw0 * 8) * 3;
#pragma unroll
    for (int i = 0; i < 6; i++) {
        int idx4 = tid + i * 256;
        int row  = idx4 / 192;
        int c4   = idx4 - row * 192;
        float4 v = *(const float4*)(stage + row * SROW + c4 * 4);
        *(float4*)(ybase + row * 1536 + c4 * 4) = v;
    }
}

extern "C" void kernel_launch(void* const* d_in, const int* in_sizes, int n_in,
                              void* d_out, int out_size)
{
    const float* x  = (const float*)d_in[0];
    const float* ql = (const float*)d_in[1];
    const float* qc = (const float*)d_in[2];

    float* y  = (float*)d_out;
    float* xq = (float*)d_out + (size_t)32 * 512 * 512 * 3;

    jpeg_kernel<<<4096, 256>>>(x, ql, qc, y, xq);
}